// round 3
// baseline (speedup 1.0000x reference)
#include <cuda_runtime.h>
#include <cuda_bf16.h>
#include <stdint.h>

// Problem constants (fixed shapes)
#define NN      8192        // nodes
#define NE      262144      // edges
#define CIN     512
#define COUT    512
#define NITEMS  (NE + NN)   // edges + self loops
#define BM_WORDS ((size_t)NN * NN / 32)   // 2,097,152 words = 8 MB bitmap

// ---------------- device scratch (no allocations allowed) ----------------
__device__ unsigned g_bitmap[BM_WORDS];      // 8 MB adjacency bitmap
__device__ int      g_deg[NN];
__device__ int      g_off[NN + 1];
__device__ int      g_cursor[NN];
__device__ float    g_dinv[NN];
__device__ int      g_cols[NITEMS];
__device__ unsigned char g_keep[NITEMS];
__device__ float    g_h[(size_t)NN * COUT];  // 16 MB: h = xW^T + b
__device__ int      g_is64;

// ---------------- clear bitmap + degree ----------------
__global__ void k_clear() {
    size_t i = (size_t)blockIdx.x * blockDim.x + threadIdx.x;
    size_t total = BM_WORDS + NN;
    for (; i < total; i += (size_t)gridDim.x * blockDim.x) {
        if (i < BM_WORDS) g_bitmap[i] = 0u;
        else              g_deg[i - BM_WORDS] = 0;
    }
}

// ---------------- detect int64 vs int32 edge_index ----------------
// If int64 (LE), the high 32-bit word of every element is 0 (values in [0,8192)).
// If int32, odd words are random node ids: P(129 consecutive odd words all 0) ~ 0.
__global__ void k_detect(const unsigned* __restrict__ e) {
    if (threadIdx.x == 0 && blockIdx.x == 0) {
        int is64 = 1;
        #pragma unroll 1
        for (int i = 1; i < 258; i += 2) {
            if (e[i] != 0u) { is64 = 0; break; }
        }
        g_is64 = is64;
    }
}

__device__ __forceinline__ void edge_rc(const void* eidx, int is64, int i, int& r, int& c) {
    if (i < NE) {
        if (is64) {
            r = (int)((const long long*)eidx)[i];
            c = (int)((const long long*)eidx)[NE + i];
        } else {
            r = ((const int*)eidx)[i];
            c = ((const int*)eidx)[NE + i];
        }
    } else {
        r = c = i - NE;   // self loop
    }
}

// ---------------- mark distinct edges, count degree ----------------
__global__ void k_mark(const void* __restrict__ eidx) {
    int i = blockIdx.x * blockDim.x + threadIdx.x;
    if (i >= NITEMS) return;
    int is64 = g_is64;
    int r, c;
    edge_rc(eidx, is64, i, r, c);
    size_t idx = (size_t)r * NN + c;
    unsigned bit = 1u << (idx & 31);
    unsigned old = atomicOr(&g_bitmap[idx >> 5], bit);
    if (!(old & bit)) {
        g_keep[i] = 1;
        atomicAdd(&g_deg[r], 1);
    } else {
        g_keep[i] = 0;
    }
}

// ---------------- exclusive scan of degrees -> CSR offsets, dinv ----------------
__global__ void k_scan() {
    __shared__ int s[1024];
    int t = threadIdx.x;
    int v[8];
    int sum = 0;
    #pragma unroll
    for (int i = 0; i < 8; i++) { v[i] = g_deg[t * 8 + i]; sum += v[i]; }
    s[t] = sum;
    __syncthreads();
    #pragma unroll 1
    for (int off = 1; off < 1024; off <<= 1) {
        int x = (t >= off) ? s[t - off] : 0;
        __syncthreads();
        s[t] += x;
        __syncthreads();
    }
    int excl = (t == 0) ? 0 : s[t - 1];
    #pragma unroll
    for (int i = 0; i < 8; i++) {
        int n = t * 8 + i;
        g_off[n]    = excl;
        g_cursor[n] = excl;
        g_dinv[n]   = rsqrtf((float)v[i]);   // deg >= 1 (self loop)
        excl += v[i];
    }
    if (t == 1023) g_off[NN] = excl;
}

// ---------------- fill CSR column list ----------------
__global__ void k_fill(const void* __restrict__ eidx) {
    int i = blockIdx.x * blockDim.x + threadIdx.x;
    if (i >= NITEMS) return;
    if (!g_keep[i]) return;
    int is64 = g_is64;
    int r, c;
    edge_rc(eidx, is64, i, r, c);
    int pos = atomicAdd(&g_cursor[r], 1);
    g_cols[pos] = c;
}

// ---------------- fp32 SGEMM: h[m][n] = sum_k x[m][k]*W[n][k] + b[n] ----------------
// 128x128 tile, BK=16, 256 threads, 8x8 per thread.
__global__ __launch_bounds__(256, 2)
void k_gemm(const float* __restrict__ A, const float* __restrict__ W,
            const float* __restrict__ bias, float* __restrict__ C) {
    const int K = CIN;
    __shared__ float As[16][128];
    __shared__ float Bs[16][128];

    int tid = threadIdx.x;
    int m0 = blockIdx.y * 128;
    int n0 = blockIdx.x * 128;
    int lr = tid >> 2;         // 0..63
    int lk = (tid & 3) << 2;   // 0,4,8,12
    int ty = tid >> 4;         // 0..15 -> rows
    int tx = tid & 15;         // 0..15 -> cols

    float acc[8][8];
    #pragma unroll
    for (int i = 0; i < 8; i++)
        #pragma unroll
        for (int j = 0; j < 8; j++) acc[i][j] = 0.f;

    const float* Ap = A + (size_t)(m0 + lr) * K + lk;
    const float* Wp = W + (size_t)(n0 + lr) * K + lk;

    #pragma unroll 1
    for (int kt = 0; kt < K; kt += 16) {
        float4 a0 = *(const float4*)(Ap + kt);
        float4 a1 = *(const float4*)(Ap + (size_t)64 * K + kt);
        float4 b0 = *(const float4*)(Wp + kt);
        float4 b1 = *(const float4*)(Wp + (size_t)64 * K + kt);

        As[lk + 0][lr] = a0.x; As[lk + 1][lr] = a0.y; As[lk + 2][lr] = a0.z; As[lk + 3][lr] = a0.w;
        As[lk + 0][lr + 64] = a1.x; As[lk + 1][lr + 64] = a1.y; As[lk + 2][lr + 64] = a1.z; As[lk + 3][lr + 64] = a1.w;
        Bs[lk + 0][lr] = b0.x; Bs[lk + 1][lr] = b0.y; Bs[lk + 2][lr] = b0.z; Bs[lk + 3][lr] = b0.w;
        Bs[lk + 0][lr + 64] = b1.x; Bs[lk + 1][lr + 64] = b1.y; Bs[lk + 2][lr + 64] = b1.z; Bs[lk + 3][lr + 64] = b1.w;
        __syncthreads();

        #pragma unroll
        for (int kk = 0; kk < 16; kk++) {
            float4 aA = *(const float4*)&As[kk][ty * 8];
            float4 aB = *(const float4*)&As[kk][ty * 8 + 4];
            float4 bA = *(const float4*)&Bs[kk][tx * 8];
            float4 bB = *(const float4*)&Bs[kk][tx * 8 + 4];
            float a[8] = {aA.x, aA.y, aA.z, aA.w, aB.x, aB.y, aB.z, aB.w};
            float b[8] = {bA.x, bA.y, bA.z, bA.w, bB.x, bB.y, bB.z, bB.w};
            #pragma unroll
            for (int i = 0; i < 8; i++)
                #pragma unroll
                for (int j = 0; j < 8; j++)
                    acc[i][j] = fmaf(a[i], b[j], acc[i][j]);
        }
        __syncthreads();
    }

    float bv[8];
    #pragma unroll
    for (int j = 0; j < 8; j++) bv[j] = bias[n0 + tx * 8 + j];

    #pragma unroll
    for (int i = 0; i < 8; i++) {
        int m = m0 + ty * 8 + i;
        float* cp = C + (size_t)m * COUT + n0 + tx * 8;
        float4 r0 = make_float4(acc[i][0] + bv[0], acc[i][1] + bv[1], acc[i][2] + bv[2], acc[i][3] + bv[3]);
        float4 r1 = make_float4(acc[i][4] + bv[4], acc[i][5] + bv[5], acc[i][6] + bv[6], acc[i][7] + bv[7]);
        *(float4*)cp = r0;
        *(float4*)(cp + 4) = r1;
    }
}

// ---------------- aggregation: out[r] = dinv[r] * sum_{c in N(r)} dinv[c] * h[c] ----------------
// One block per row, 128 threads (float4 each -> 512 channels).
__global__ __launch_bounds__(128)
void k_agg(const float* __restrict__ h, float* __restrict__ out) {
    __shared__ int   sc[256];
    __shared__ float sd[256];
    int r = blockIdx.x;
    int t = threadIdx.x;
    int beg = g_off[r], end = g_off[r + 1];
    float4 acc = make_float4(0.f, 0.f, 0.f, 0.f);

    for (int base = beg; base < end; base += 256) {
        int cnt = min(256, end - base);
        for (int j = t; j < cnt; j += 128) {
            int c = g_cols[base + j];
            sc[j] = c;
            sd[j] = g_dinv[c];
        }
        __syncthreads();
        #pragma unroll 4
        for (int j = 0; j < cnt; j++) {
            const float4* hv = (const float4*)(h + (size_t)sc[j] * COUT);
            float s = sd[j];
            float4 v = hv[t];
            acc.x = fmaf(s, v.x, acc.x);
            acc.y = fmaf(s, v.y, acc.y);
            acc.z = fmaf(s, v.z, acc.z);
            acc.w = fmaf(s, v.w, acc.w);
        }
        __syncthreads();
    }

    float dr = g_dinv[r];
    ((float4*)(out + (size_t)r * COUT))[t] =
        make_float4(dr * acc.x, dr * acc.y, dr * acc.z, dr * acc.w);
}

// ---------------- launch ----------------
extern "C" void kernel_launch(void* const* d_in, const int* in_sizes, int n_in,
                              void* d_out, int out_size) {
    const float* x    = (const float*)d_in[0];
    const void*  eidx = d_in[1];
    const float* W    = (const float*)d_in[2];
    const float* b    = (const float*)d_in[3];
    float* out = (float*)d_out;

    float* h_ptr;
    cudaGetSymbolAddress((void**)&h_ptr, g_h);

    // 1. clear bitmap + degrees
    {
        size_t total = BM_WORDS + NN;
        int threads = 256;
        int blocks = (int)((total + threads - 1) / threads);
        k_clear<<<blocks, threads>>>();
    }
    // 2. detect edge dtype
    k_detect<<<1, 32>>>((const unsigned*)eidx);
    // 3. mark distinct edges + degree
    {
        int threads = 256;
        int blocks = (NITEMS + threads - 1) / threads;
        k_mark<<<blocks, threads>>>(eidx);
    }
    // 4. scan -> CSR offsets, cursors, dinv
    k_scan<<<1, 1024>>>();
    // 5. fill CSR cols
    {
        int threads = 256;
        int blocks = (NITEMS + threads - 1) / threads;
        k_fill<<<blocks, threads>>>(eidx);
    }
    // 6. h = x W^T + b
    {
        dim3 grid(COUT / 128, NN / 128);  // (4, 64)
        k_gemm<<<grid, 256>>>(x, W, b, h_ptr);
    }
    // 7. aggregate
    k_agg<<<NN, 128>>>(h_ptr, out);
}

// round 5
// speedup vs baseline: 1.5758x; 1.5758x over previous
#include <cuda_runtime.h>
#include <cuda_bf16.h>
#include <stdint.h>

// Problem constants (fixed shapes)
#define NN      8192        // nodes
#define NE      262144      // edges
#define CIN     512
#define COUT    512
#define NITEMS  (NE + NN)   // edges + self loops
#define BM_WORDS ((size_t)NN * NN / 32)   // 2,097,152 words = 8 MB bitmap

// ---------------- device scratch (no allocations allowed) ----------------
__device__ unsigned g_bitmap[BM_WORDS];      // 8 MB adjacency bitmap
__device__ int      g_deg[NN];
__device__ int      g_off[NN + 1];
__device__ int      g_cursor[NN];
__device__ float    g_dinv[NN];
__device__ int      g_cols[NITEMS];
__device__ unsigned char g_keep[NITEMS];
__device__ float    g_h[(size_t)NN * COUT];  // 16 MB: h = xW^T + b
__device__ int      g_is64;

// ---------------- clear bitmap + degree (vectorized) ----------------
__global__ void k_clear() {
    size_t i = (size_t)blockIdx.x * blockDim.x + threadIdx.x;
    uint4 z = make_uint4(0u, 0u, 0u, 0u);
    if (i < BM_WORDS / 4) ((uint4*)g_bitmap)[i] = z;
    if (i < NN) g_deg[i] = 0;
}

// ---------------- detect int64 vs int32 edge_index (parallel ballot) ----------------
// If int64 (LE), high words of elements are 0 (ids < 8192). If int32, odd words
// are random ids: P(128 random ids all zero) = 8192^-128 ~ 0.
__global__ void k_detect(const unsigned* __restrict__ e) {
    unsigned v = e[threadIdx.x * 2 + 1];
    int any = __syncthreads_or(v != 0u);
    if (threadIdx.x == 0) g_is64 = !any;
}

__device__ __forceinline__ void edge_rc(const void* eidx, int is64, int i, int& r, int& c) {
    if (i < NE) {
        if (is64) {
            r = (int)((const long long*)eidx)[i];
            c = (int)((const long long*)eidx)[NE + i];
        } else {
            r = ((const int*)eidx)[i];
            c = ((const int*)eidx)[NE + i];
        }
    } else {
        r = c = i - NE;   // self loop
    }
}

// ---------------- mark distinct edges, count degree ----------------
__global__ void k_mark(const void* __restrict__ eidx) {
    int i = blockIdx.x * blockDim.x + threadIdx.x;
    if (i >= NITEMS) return;
    int is64 = g_is64;
    int r, c;
    edge_rc(eidx, is64, i, r, c);
    size_t idx = (size_t)r * NN + c;
    unsigned bit = 1u << (idx & 31);
    unsigned old = atomicOr(&g_bitmap[idx >> 5], bit);
    if (!(old & bit)) {
        g_keep[i] = 1;
        atomicAdd(&g_deg[r], 1);
    } else {
        g_keep[i] = 0;
    }
}

// ---------------- exclusive scan of degrees -> CSR offsets, dinv ----------------
// 1024 threads x 8 values, warp-shuffle two-level scan (2 barriers).
__global__ void k_scan() {
    __shared__ int wsum[32];
    int t = threadIdx.x;
    int lane = t & 31, wid = t >> 5;
    int v[8];
    int s = 0;
    #pragma unroll
    for (int i = 0; i < 8; i++) { v[i] = g_deg[t * 8 + i]; s += v[i]; }

    // inclusive warp scan of per-thread sums
    int x = s;
    #pragma unroll
    for (int off = 1; off < 32; off <<= 1) {
        int y = __shfl_up_sync(0xffffffffu, x, off);
        if (lane >= off) x += y;
    }
    if (lane == 31) wsum[wid] = x;
    __syncthreads();
    if (wid == 0) {
        int y = wsum[lane];
        #pragma unroll
        for (int off = 1; off < 32; off <<= 1) {
            int z = __shfl_up_sync(0xffffffffu, y, off);
            if (lane >= off) y += z;
        }
        wsum[lane] = y;
    }
    __syncthreads();

    int excl = (wid ? wsum[wid - 1] : 0) + x - s;  // exclusive prefix for this thread
    #pragma unroll
    for (int i = 0; i < 8; i++) {
        int n = t * 8 + i;
        g_off[n]    = excl;
        g_cursor[n] = excl;
        g_dinv[n]   = rsqrtf((float)v[i]);   // deg >= 1 (self loop)
        excl += v[i];
    }
    if (t == 1023) g_off[NN] = wsum[31];
}

// ---------------- fill CSR column list ----------------
__global__ void k_fill(const void* __restrict__ eidx) {
    int i = blockIdx.x * blockDim.x + threadIdx.x;
    if (i >= NITEMS) return;
    if (!g_keep[i]) return;
    int is64 = g_is64;
    int r, c;
    edge_rc(eidx, is64, i, r, c);
    int pos = atomicAdd(&g_cursor[r], 1);
    g_cols[pos] = c;
}

// ---------------- tensor-core GEMM: h = x W^T + b via bf16 3-term split ----------------
// x = b1 + b2 + O(2^-18).  x*W ~= b1*W1 + b1*W2 + b2*W1  (error ~2^-18 per product).
// mma.sync.m16n8k16 row.col f32.bf16.bf16.f32. Block tile 128x128, BK=32,
// 256 threads = 8 warps, each warp 64x32 (4x4 m16n8 tiles).
#define BKP 40   // smem row stride in bf16 elems (conflict-free for k-pair loads)

__device__ __forceinline__ void mma_bf16(float* c, const unsigned* a, const unsigned* b) {
    asm volatile(
        "mma.sync.aligned.m16n8k16.row.col.f32.bf16.bf16.f32 "
        "{%0,%1,%2,%3}, {%4,%5,%6,%7}, {%8,%9}, {%0,%1,%2,%3};"
        : "+f"(c[0]), "+f"(c[1]), "+f"(c[2]), "+f"(c[3])
        : "r"(a[0]), "r"(a[1]), "r"(a[2]), "r"(a[3]), "r"(b[0]), "r"(b[1]));
}

__device__ __forceinline__ unsigned pack_split(float x, float y, unsigned& lo_pack) {
    __nv_bfloat16 hx = __float2bfloat16(x);
    __nv_bfloat16 hy = __float2bfloat16(y);
    __nv_bfloat16 lx = __float2bfloat16(x - __bfloat162float(hx));
    __nv_bfloat16 ly = __float2bfloat16(y - __bfloat162float(hy));
    __nv_bfloat162 hi2 = __nv_bfloat162(hx, hy);
    __nv_bfloat162 lo2 = __nv_bfloat162(lx, ly);
    lo_pack = *(unsigned*)&lo2;
    return *(unsigned*)&hi2;
}

__global__ __launch_bounds__(256)
void k_gemm_tc(const float* __restrict__ A, const float* __restrict__ W,
               const float* __restrict__ bias, float* __restrict__ C) {
    __shared__ __nv_bfloat16 sA1[128 * BKP];
    __shared__ __nv_bfloat16 sA2[128 * BKP];
    __shared__ __nv_bfloat16 sB1[128 * BKP];
    __shared__ __nv_bfloat16 sB2[128 * BKP];

    int tid = threadIdx.x;
    int m0 = blockIdx.y * 128;
    int n0 = blockIdx.x * 128;
    int lane = tid & 31, w = tid >> 5;
    int wm = (w & 1) * 64;       // warp row offset
    int wn = (w >> 1) * 32;      // warp col offset
    int g  = lane >> 2;          // 0..7
    int tg = lane & 3;           // 0..3

    float acc[4][4][4];
    #pragma unroll
    for (int mi = 0; mi < 4; mi++)
        #pragma unroll
        for (int ni = 0; ni < 4; ni++)
            #pragma unroll
            for (int q = 0; q < 4; q++) acc[mi][ni][q] = 0.f;

    int lr = tid >> 3;          // 0..31 (row within 32-row group)
    int lc = (tid & 7) * 4;     // k offset 0..28

    #pragma unroll 1
    for (int kt = 0; kt < CIN; kt += 32) {
        #pragma unroll
        for (int rr = 0; rr < 4; rr++) {
            int r = lr + rr * 32;
            float4 va = *(const float4*)(A + (size_t)(m0 + r) * CIN + kt + lc);
            float4 vb = *(const float4*)(W + (size_t)(n0 + r) * CIN + kt + lc);
            unsigned lo;
            unsigned hi;
            hi = pack_split(va.x, va.y, lo);
            *(unsigned*)&sA1[r * BKP + lc]     = hi; *(unsigned*)&sA2[r * BKP + lc]     = lo;
            hi = pack_split(va.z, va.w, lo);
            *(unsigned*)&sA1[r * BKP + lc + 2] = hi; *(unsigned*)&sA2[r * BKP + lc + 2] = lo;
            hi = pack_split(vb.x, vb.y, lo);
            *(unsigned*)&sB1[r * BKP + lc]     = hi; *(unsigned*)&sB2[r * BKP + lc]     = lo;
            hi = pack_split(vb.z, vb.w, lo);
            *(unsigned*)&sB1[r * BKP + lc + 2] = hi; *(unsigned*)&sB2[r * BKP + lc + 2] = lo;
        }
        __syncthreads();

        #pragma unroll
        for (int ks = 0; ks < 2; ks++) {
            int k0 = ks * 16 + tg * 2;
            unsigned a1f[4][4], a2f[4][4];
            #pragma unroll
            for (int mi = 0; mi < 4; mi++) {
                int r0 = wm + mi * 16 + g;
                a1f[mi][0] = *(unsigned*)&sA1[r0 * BKP + k0];
                a1f[mi][1] = *(unsigned*)&sA1[(r0 + 8) * BKP + k0];
                a1f[mi][2] = *(unsigned*)&sA1[r0 * BKP + k0 + 8];
                a1f[mi][3] = *(unsigned*)&sA1[(r0 + 8) * BKP + k0 + 8];
                a2f[mi][0] = *(unsigned*)&sA2[r0 * BKP + k0];
                a2f[mi][1] = *(unsigned*)&sA2[(r0 + 8) * BKP + k0];
                a2f[mi][2] = *(unsigned*)&sA2[r0 * BKP + k0 + 8];
                a2f[mi][3] = *(unsigned*)&sA2[(r0 + 8) * BKP + k0 + 8];
            }
            unsigned b1f[4][2], b2f[4][2];
            #pragma unroll
            for (int ni = 0; ni < 4; ni++) {
                int c = wn + ni * 8 + g;
                b1f[ni][0] = *(unsigned*)&sB1[c * BKP + k0];
                b1f[ni][1] = *(unsigned*)&sB1[c * BKP + k0 + 8];
                b2f[ni][0] = *(unsigned*)&sB2[c * BKP + k0];
                b2f[ni][1] = *(unsigned*)&sB2[c * BKP + k0 + 8];
            }
            #pragma unroll
            for (int mi = 0; mi < 4; mi++)
                #pragma unroll
                for (int ni = 0; ni < 4; ni++) {
                    mma_bf16(acc[mi][ni], a1f[mi], b1f[ni]);  // hi*hi
                    mma_bf16(acc[mi][ni], a1f[mi], b2f[ni]);  // hi*lo
                    mma_bf16(acc[mi][ni], a2f[mi], b1f[ni]);  // lo*hi
                }
        }
        __syncthreads();
    }

    // epilogue: add bias, write fp32
    #pragma unroll
    for (int mi = 0; mi < 4; mi++) {
        int r0 = m0 + wm + mi * 16 + g;
        #pragma unroll
        for (int ni = 0; ni < 4; ni++) {
            int col = n0 + wn + ni * 8 + tg * 2;
            float b0 = bias[col], b1 = bias[col + 1];
            float* p0 = C + (size_t)r0 * COUT + col;
            float* p1 = C + (size_t)(r0 + 8) * COUT + col;
            p0[0] = acc[mi][ni][0] + b0;
            p0[1] = acc[mi][ni][1] + b1;
            p1[0] = acc[mi][ni][2] + b0;
            p1[1] = acc[mi][ni][3] + b1;
        }
    }
}

// ---------------- aggregation: out[r] = dinv[r] * sum_{c in N(r)} dinv[c] * h[c] ----------------
__global__ __launch_bounds__(128)
void k_agg(const float* __restrict__ h, float* __restrict__ out) {
    __shared__ int   sc[256];
    __shared__ float sd[256];
    int r = blockIdx.x;
    int t = threadIdx.x;
    int beg = g_off[r], end = g_off[r + 1];
    float4 acc = make_float4(0.f, 0.f, 0.f, 0.f);

    for (int base = beg; base < end; base += 256) {
        int cnt = min(256, end - base);
        for (int j = t; j < cnt; j += 128) {
            int c = g_cols[base + j];
            sc[j] = c;
            sd[j] = g_dinv[c];
        }
        __syncthreads();
        #pragma unroll 4
        for (int j = 0; j < cnt; j++) {
            const float4* hv = (const float4*)(h + (size_t)sc[j] * COUT);
            float s = sd[j];
            float4 v = hv[t];
            acc.x = fmaf(s, v.x, acc.x);
            acc.y = fmaf(s, v.y, acc.y);
            acc.z = fmaf(s, v.z, acc.z);
            acc.w = fmaf(s, v.w, acc.w);
        }
        __syncthreads();
    }

    float dr = g_dinv[r];
    ((float4*)(out + (size_t)r * COUT))[t] =
        make_float4(dr * acc.x, dr * acc.y, dr * acc.z, dr * acc.w);
}

// ---------------- launch ----------------
extern "C" void kernel_launch(void* const* d_in, const int* in_sizes, int n_in,
                              void* d_out, int out_size) {
    const float* x    = (const float*)d_in[0];
    const void*  eidx = d_in[1];
    const float* W    = (const float*)d_in[2];
    const float* b    = (const float*)d_in[3];
    float* out = (float*)d_out;

    float* h_ptr;
    cudaGetSymbolAddress((void**)&h_ptr, g_h);

    // 1. GEMM first (independent of edge pipeline)
    {
        dim3 grid(COUT / 128, NN / 128);  // (4, 64)
        k_gemm_tc<<<grid, 256>>>(x, W, b, h_ptr);
    }
    // 2. clear bitmap + degrees
    {
        size_t total4 = BM_WORDS / 4;  // uint4 stores
        int threads = 256;
        int blocks = (int)((total4 + threads - 1) / threads);
        k_clear<<<blocks, threads>>>();
    }
    // 3. detect edge dtype
    k_detect<<<1, 128>>>((const unsigned*)eidx);
    // 4. mark distinct edges + degree
    {
        int threads = 256;
        int blocks = (NITEMS + threads - 1) / threads;
        k_mark<<<blocks, threads>>>(eidx);
    }
    // 5. scan -> CSR offsets, cursors, dinv
    k_scan<<<1, 1024>>>();
    // 6. fill CSR cols
    {
        int threads = 256;
        int blocks = (NITEMS + threads - 1) / threads;
        k_fill<<<blocks, threads>>>(eidx);
    }
    // 7. aggregate
    k_agg<<<NN, 128>>>(h_ptr, out);
}